// round 1
// baseline (speedup 1.0000x reference)
#include <cuda_runtime.h>
#include <cstdint>

#define N_NODES 100000
#define N_EDGES 20000
#define NNZ     800000
#define D       128

// Scratch (allocation-free rule: __device__ globals)
__device__ __align__(16) float g_Xe[N_EDGES * D];   // 10.24 MB
__device__ __align__(16) float g_Xv[N_NODES * D];   // 51.2 MB

// ---------------------------------------------------------------------------
// Zero scratch
// ---------------------------------------------------------------------------
__global__ void zero_kernel() {
    const int XE4 = N_EDGES * D / 4;        // 640,000
    const int TOT = XE4 + N_NODES * D / 4;  // 3,840,000
    int i = blockIdx.x * blockDim.x + threadIdx.x;
    float4 z = make_float4(0.f, 0.f, 0.f, 0.f);
    if (i < XE4)      reinterpret_cast<float4*>(g_Xe)[i] = z;
    else if (i < TOT) reinterpret_cast<float4*>(g_Xv)[i - XE4] = z;
}

// ---------------------------------------------------------------------------
// Vector reduction helper: red.global.add.v4.f32 (sm_90+)
// ---------------------------------------------------------------------------
__device__ __forceinline__ void red_add_v4(float* p, float4 v) {
    asm volatile("red.global.add.v4.f32 [%0], {%1, %2, %3, %4};"
                 :: "l"(p), "f"(v.x), "f"(v.y), "f"(v.z), "f"(v.w)
                 : "memory");
}

// ---------------------------------------------------------------------------
// Scatter 1: Xe[g1_dst] += X[g1_src]        (warp per nonzero, float4/lane)
// ---------------------------------------------------------------------------
__global__ void scatter1_kernel(const float4* __restrict__ X4,
                                const int* __restrict__ src,
                                const int* __restrict__ dst) {
    int w = (blockIdx.x * blockDim.x + threadIdx.x) >> 5;
    if (w >= NNZ) return;
    int lane = threadIdx.x & 31;
    int s = __ldg(src + w);
    int d = __ldg(dst + w);
    float4 v = __ldg(X4 + s * 32 + lane);
    red_add_v4(g_Xe + d * 128 + lane * 4, v);
}

// ---------------------------------------------------------------------------
// Scatter 2: Xv[g2_dst] += Xe[g2_src] * degE[g2_src]   (degE scale fused)
// ---------------------------------------------------------------------------
__global__ void scatter2_kernel(const float* __restrict__ degE,
                                const int* __restrict__ src,
                                const int* __restrict__ dst) {
    int w = (blockIdx.x * blockDim.x + threadIdx.x) >> 5;
    if (w >= NNZ) return;
    int lane = threadIdx.x & 31;
    int s = __ldg(src + w);
    int d = __ldg(dst + w);
    float de = __ldg(degE + s);
    float4 v = reinterpret_cast<const float4*>(g_Xe)[s * 32 + lane];
    v.x *= de; v.y *= de; v.z *= de; v.w *= de;
    red_add_v4(g_Xv + d * 128 + lane * 4, v);
}

// ---------------------------------------------------------------------------
// Final phase: Xi = (1-a)*degV*Xv + a*X0 ;  out = (1-b)*Xi + b*(Xi @ W^T)
// tf32 mma only for the b-scaled matmul term; residual stays exact fp32.
// Block = 128 threads (4 warps), tile = 64 rows x 128 cols, K = 128.
// ---------------------------------------------------------------------------
__device__ __forceinline__ uint32_t f2tf32(float f) {
    uint32_t r;
    asm("cvt.rna.tf32.f32 %0, %1;" : "=r"(r) : "f"(f));
    return r;
}

#define W_STRIDE  132            // padded to keep frag loads conflict-free
#define XI_STRIDE 132
#define GEMM_SMEM ((128 * W_STRIDE + 64 * XI_STRIDE) * 4)   // 101,376 B

__global__ void gemm_kernel(const float* __restrict__ X0,
                            const float* __restrict__ degV,
                            const float* __restrict__ alpha,
                            const float* __restrict__ beta,
                            const float* __restrict__ W,
                            float* __restrict__ out) {
    extern __shared__ float sm[];
    float* Wsm  = sm;                    // [k][n], stride 132, tf32-rounded
    float* Xism = sm + 128 * W_STRIDE;   // [r][c], stride 132, exact fp32

    const int tid = threadIdx.x;
    const float a  = __ldg(alpha);
    const float bb = __ldg(beta);

    // Stage W^T as B (k x n), tf32-rounded. B[k][n] = W[n][k].
    for (int j = tid; j < 128 * 128; j += 128) {
        int n = j >> 7, k = j & 127;
        uint32_t t = f2tf32(__ldg(W + j));         // W row-major [n][k]
        Wsm[k * W_STRIDE + n] = __uint_as_float(t);
    }

    // Stage Xi tile (64 rows), exact fp32
    const int row0 = blockIdx.x * 64;
    const float oma = 1.f - a;
    for (int i = tid; i < 64 * 32; i += 128) {     // float4 granules
        int r = i >> 5, c4 = i & 31;
        int gr = row0 + r;
        float4 xi = make_float4(0.f, 0.f, 0.f, 0.f);
        if (gr < N_NODES) {
            float4 xv = reinterpret_cast<const float4*>(g_Xv)[gr * 32 + c4];
            float4 x0 = __ldg(reinterpret_cast<const float4*>(X0) + gr * 32 + c4);
            float s = oma * __ldg(degV + gr);
            xi.x = s * xv.x + a * x0.x;
            xi.y = s * xv.y + a * x0.y;
            xi.z = s * xv.z + a * x0.z;
            xi.w = s * xv.w + a * x0.w;
        }
        *reinterpret_cast<float4*>(&Xism[r * XI_STRIDE + c4 * 4]) = xi;
    }
    __syncthreads();

    const int warp = tid >> 5, lane = tid & 31;
    const int gid = lane >> 2, tig = lane & 3;
    const int wrow = warp * 16;

    // Preload A fragments for all 16 k-steps (tf32)
    uint32_t afr[16][4];
#pragma unroll
    for (int kk = 0; kk < 16; kk++) {
        int c = kk * 8 + tig;
        afr[kk][0] = f2tf32(Xism[(wrow + gid)     * XI_STRIDE + c]);
        afr[kk][1] = f2tf32(Xism[(wrow + gid + 8) * XI_STRIDE + c]);
        afr[kk][2] = f2tf32(Xism[(wrow + gid)     * XI_STRIDE + c + 4]);
        afr[kk][3] = f2tf32(Xism[(wrow + gid + 8) * XI_STRIDE + c + 4]);
    }

    const float omb = 1.f - bb;
    const int r0 = row0 + wrow + gid;
    const int r1 = r0 + 8;

#pragma unroll 4
    for (int nt = 0; nt < 16; nt++) {
        float c0 = 0.f, c1 = 0.f, c2 = 0.f, c3 = 0.f;
#pragma unroll
        for (int kk = 0; kk < 16; kk++) {
            uint32_t b0 = __float_as_uint(Wsm[(kk * 8 + tig)     * W_STRIDE + nt * 8 + gid]);
            uint32_t b1 = __float_as_uint(Wsm[(kk * 8 + tig + 4) * W_STRIDE + nt * 8 + gid]);
            asm volatile(
                "mma.sync.aligned.m16n8k8.row.col.f32.tf32.tf32.f32 "
                "{%0,%1,%2,%3}, {%4,%5,%6,%7}, {%8,%9}, {%0,%1,%2,%3};"
                : "+f"(c0), "+f"(c1), "+f"(c2), "+f"(c3)
                : "r"(afr[kk][0]), "r"(afr[kk][1]), "r"(afr[kk][2]), "r"(afr[kk][3]),
                  "r"(b0), "r"(b1));
        }
        int col = nt * 8 + 2 * tig;
        if (r0 < N_NODES) {
            float xi0 = Xism[(wrow + gid) * XI_STRIDE + col];
            float xi1 = Xism[(wrow + gid) * XI_STRIDE + col + 1];
            float2 o = make_float2(omb * xi0 + bb * c0, omb * xi1 + bb * c1);
            *reinterpret_cast<float2*>(out + (long)r0 * 128 + col) = o;
        }
        if (r1 < N_NODES) {
            float xi0 = Xism[(wrow + gid + 8) * XI_STRIDE + col];
            float xi1 = Xism[(wrow + gid + 8) * XI_STRIDE + col + 1];
            float2 o = make_float2(omb * xi0 + bb * c2, omb * xi1 + bb * c3);
            *reinterpret_cast<float2*>(out + (long)r1 * 128 + col) = o;
        }
    }
}

// ---------------------------------------------------------------------------
// kernel_launch
// ---------------------------------------------------------------------------
extern "C" void kernel_launch(void* const* d_in, const int* in_sizes, int n_in,
                              void* d_out, int out_size) {
    const float* X     = (const float*)d_in[0];
    const float* X0    = (const float*)d_in[1];
    const float* degE  = (const float*)d_in[2];
    const float* degV  = (const float*)d_in[3];
    const float* alpha = (const float*)d_in[4];
    const float* beta  = (const float*)d_in[5];
    const float* W     = (const float*)d_in[6];
    const int*   g1s   = (const int*)d_in[7];
    const int*   g1d   = (const int*)d_in[8];
    const int*   g2s   = (const int*)d_in[9];
    const int*   g2d   = (const int*)d_in[10];
    float* out = (float*)d_out;

    cudaFuncSetAttribute(gemm_kernel,
                         cudaFuncAttributeMaxDynamicSharedMemorySize, GEMM_SMEM);

    // 1. zero scratch (3.84M float4)
    zero_kernel<<<15000, 256>>>();

    // 2. scatter X -> Xe  (1 warp per nnz, 8 nnz per block)
    scatter1_kernel<<<NNZ / 8, 256>>>((const float4*)X, g1s, g1d);

    // 3. scatter Xe*degE -> Xv
    scatter2_kernel<<<NNZ / 8, 256>>>(degE, g2s, g2d);

    // 4. Xi formation + tf32 GEMM + residual epilogue
    gemm_kernel<<<(N_NODES + 63) / 64, 128, GEMM_SMEM>>>(X0, degV, alpha, beta, W, out);
}